// round 4
// baseline (speedup 1.0000x reference)
#include <cuda_runtime.h>
#include <cuda_bf16.h>

// Problem constants (shapes fixed by the dataset)
#define NMAX 20000
#define EMAX 320000
#define DIM  300
#define HD   600            // H * DIM, H = 2
#define ETMAX (EMAX + NMAX) // edges + self loops
#define NEG_SLOPE 0.2f

// -------- device scratch (static; referenced directly by name) --------
__device__ float g_xp[(size_t)NMAX * HD];   // projected features [N, H*D] = 48 MB
__device__ float g_asrc[NMAX * 2];          // per-node src logits (per head)
__device__ float g_adst[NMAX * 2];          // per-node dst logits (per head)
__device__ int   g_deg[NMAX];
__device__ int   g_offs[NMAX + 1];
__device__ int   g_cursor[NMAX + 1];
__device__ int   g_csr_src[ETMAX];          // src node per CSR slot (grouped by dst)

// ============================================================
// Kernel 1: tiled fp32 GEMM  g_xp[M,600] = A[M,300] * B[300,600]
// ============================================================
#define BM 64
#define BN 64
#define BK 12
__global__ void gemm_kernel(const float* __restrict__ A,
                            const float* __restrict__ B, int M) {
    __shared__ float As[BK][BM];
    __shared__ float Bs[BK][BN];

    const int tx = threadIdx.x & 15;       // 0..15
    const int ty = threadIdx.x >> 4;       // 0..15
    const int row0 = blockIdx.y * BM;
    const int col0 = blockIdx.x * BN;

    float acc[4][4];
#pragma unroll
    for (int i = 0; i < 4; i++)
#pragma unroll
        for (int j = 0; j < 4; j++) acc[i][j] = 0.f;

    for (int k0 = 0; k0 < DIM; k0 += BK) {
#pragma unroll
        for (int i = threadIdx.x; i < BM * BK; i += 256) {
            int r = i / BK, c = i % BK;
            int gr = row0 + r;
            As[c][r] = (gr < M) ? A[(size_t)gr * DIM + k0 + c] : 0.f;
        }
#pragma unroll
        for (int i = threadIdx.x; i < BK * BN; i += 256) {
            int r = i / BN, c = i % BN;
            int gc = col0 + c;
            Bs[r][c] = (gc < HD) ? B[(size_t)(k0 + r) * HD + gc] : 0.f;
        }
        __syncthreads();
#pragma unroll
        for (int k = 0; k < BK; k++) {
            float a[4], b[4];
#pragma unroll
            for (int i = 0; i < 4; i++) a[i] = As[k][ty * 4 + i];
#pragma unroll
            for (int j = 0; j < 4; j++) b[j] = Bs[k][tx * 4 + j];
#pragma unroll
            for (int i = 0; i < 4; i++)
#pragma unroll
                for (int j = 0; j < 4; j++) acc[i][j] += a[i] * b[j];
        }
        __syncthreads();
    }
#pragma unroll
    for (int i = 0; i < 4; i++) {
        int r = row0 + ty * 4 + i;
        if (r >= M) continue;
#pragma unroll
        for (int j = 0; j < 4; j++) {
            int c = col0 + tx * 4 + j;
            if (c < HD) g_xp[(size_t)r * HD + c] = acc[i][j];
        }
    }
}

// ============================================================
// Kernel 2: per-node attention logits (warp per node)
// ============================================================
__global__ void logits_kernel(const float* __restrict__ att_src,
                              const float* __restrict__ att_dst, int n) {
    int gtid = blockIdx.x * blockDim.x + threadIdx.x;
    int node = gtid >> 5;
    int lane = gtid & 31;
    if (node >= n) return;
    const float* row = g_xp + (size_t)node * HD;
    float s0 = 0.f, s1 = 0.f, d0 = 0.f, d1 = 0.f;
    for (int c = lane; c < DIM; c += 32) {
        float v0 = row[c], v1 = row[DIM + c];
        s0 += v0 * att_src[c];
        s1 += v1 * att_src[DIM + c];
        d0 += v0 * att_dst[c];
        d1 += v1 * att_dst[DIM + c];
    }
#pragma unroll
    for (int o = 16; o > 0; o >>= 1) {
        s0 += __shfl_down_sync(0xffffffffu, s0, o);
        s1 += __shfl_down_sync(0xffffffffu, s1, o);
        d0 += __shfl_down_sync(0xffffffffu, d0, o);
        d1 += __shfl_down_sync(0xffffffffu, d1, o);
    }
    if (lane == 0) {
        g_asrc[node * 2 + 0] = s0;
        g_asrc[node * 2 + 1] = s1;
        g_adst[node * 2 + 0] = d0;
        g_adst[node * 2 + 1] = d1;
    }
}

// ============================================================
// Kernel 3: zero degree array
// ============================================================
__global__ void zero_deg_kernel(int n) {
    int i = blockIdx.x * blockDim.x + threadIdx.x;
    if (i < n) g_deg[i] = 0;
}

// ============================================================
// Kernel 4: histogram of dst (edges + self loops) — edge_index is int32
// ============================================================
__global__ void hist_kernel(const int* __restrict__ ei, int e, int n) {
    int i = blockIdx.x * blockDim.x + threadIdx.x;
    int total = e + n;
    if (i >= total) return;
    int d = (i < e) ? ei[e + i] : (i - e);
    atomicAdd(&g_deg[d], 1);
}

// ============================================================
// Kernel 5: single-block exclusive scan -> offsets + cursor init
// ============================================================
__global__ void scan_kernel(int n) {
    __shared__ int sh[1024];
    __shared__ int carry;
    int t = threadIdx.x;
    if (t == 0) { carry = 0; g_offs[0] = 0; g_cursor[0] = 0; }
    __syncthreads();
    for (int base = 0; base < n; base += 1024) {
        int i = base + t;
        int v = (i < n) ? g_deg[i] : 0;
        sh[t] = v;
        __syncthreads();
#pragma unroll
        for (int off = 1; off < 1024; off <<= 1) {
            int add = (t >= off) ? sh[t - off] : 0;
            __syncthreads();
            sh[t] += add;
            __syncthreads();
        }
        int incl = sh[t] + carry;
        if (i < n) { g_offs[i + 1] = incl; g_cursor[i + 1] = incl; }
        __syncthreads();
        if (t == 1023) carry = incl;
        __syncthreads();
    }
}

// ============================================================
// Kernel 6: scatter edges into CSR-by-dst — edge_index is int32
// ============================================================
__global__ void scatter_kernel(const int* __restrict__ ei, int e, int n) {
    int i = blockIdx.x * blockDim.x + threadIdx.x;
    int total = e + n;
    if (i >= total) return;
    int s, d;
    if (i < e) {
        s = ei[i];
        d = ei[e + i];
    } else {
        s = d = i - e;
    }
    int pos = atomicAdd(&g_cursor[d], 1);
    g_csr_src[pos] = s;
}

// ============================================================
// Kernel 7: fused segment softmax + weighted aggregation + epilogue
// ============================================================
#define CAP 256
__global__ void agg_kernel(const float* __restrict__ bias,
                           const float* __restrict__ lin_w,
                           const float* __restrict__ lin_b,
                           float* __restrict__ out, int n) {
    int node = blockIdx.x;
    if (node >= n) return;
    int t = threadIdx.x;

    int beg = g_offs[node];
    int deg = g_offs[node + 1] - beg;

    float ad0 = g_adst[node * 2 + 0];
    float ad1 = g_adst[node * 2 + 1];

    __shared__ float sh_e0[CAP];
    __shared__ float sh_e1[CAP];
    __shared__ int   sh_s[CAP];
    __shared__ float r0[128];
    __shared__ float r1[128];

    // ---- phase 1: logits + per-head max ----
    float m0 = -3.4e38f, m1 = -3.4e38f;
    for (int j = t; j < deg; j += 128) {
        int s = g_csr_src[beg + j];
        float z0 = g_asrc[s * 2 + 0] + ad0;
        float z1 = g_asrc[s * 2 + 1] + ad1;
        z0 = (z0 > 0.f) ? z0 : NEG_SLOPE * z0;
        z1 = (z1 > 0.f) ? z1 : NEG_SLOPE * z1;
        m0 = fmaxf(m0, z0);
        m1 = fmaxf(m1, z1);
        if (j < CAP) { sh_e0[j] = z0; sh_e1[j] = z1; sh_s[j] = s; }
    }
    r0[t] = m0; r1[t] = m1;
    __syncthreads();
#pragma unroll
    for (int s = 64; s > 0; s >>= 1) {
        if (t < s) {
            r0[t] = fmaxf(r0[t], r0[t + s]);
            r1[t] = fmaxf(r1[t], r1[t + s]);
        }
        __syncthreads();
    }
    float M0 = r0[0], M1 = r1[0];
    __syncthreads();

    // ---- phase 2: exp and sum ----
    float s0 = 0.f, s1 = 0.f;
    for (int j = t; j < deg; j += 128) {
        float e0, e1;
        if (j < CAP) {
            e0 = __expf(sh_e0[j] - M0);
            e1 = __expf(sh_e1[j] - M1);
            sh_e0[j] = e0;
            sh_e1[j] = e1;
        } else {
            int s = g_csr_src[beg + j];
            float z0 = g_asrc[s * 2 + 0] + ad0;
            float z1 = g_asrc[s * 2 + 1] + ad1;
            z0 = (z0 > 0.f) ? z0 : NEG_SLOPE * z0;
            z1 = (z1 > 0.f) ? z1 : NEG_SLOPE * z1;
            e0 = __expf(z0 - M0);
            e1 = __expf(z1 - M1);
        }
        s0 += e0; s1 += e1;
    }
    r0[t] = s0; r1[t] = s1;
    __syncthreads();
#pragma unroll
    for (int s = 64; s > 0; s >>= 1) {
        if (t < s) {
            r0[t] += r0[t + s];
            r1[t] += r1[t + s];
        }
        __syncthreads();
    }
    float inv0 = 1.f / r0[0];
    float inv1 = 1.f / r1[0];
    __syncthreads();

    // ---- phase 3: weighted gather of xp rows ----
    float acc0[3] = {0.f, 0.f, 0.f};
    float acc1[3] = {0.f, 0.f, 0.f};
    for (int j = 0; j < deg; j++) {
        int s;
        float w0, w1;
        if (j < CAP) {
            s = sh_s[j];
            w0 = sh_e0[j] * inv0;
            w1 = sh_e1[j] * inv1;
        } else {
            s = g_csr_src[beg + j];
            float z0 = g_asrc[s * 2 + 0] + ad0;
            float z1 = g_asrc[s * 2 + 1] + ad1;
            z0 = (z0 > 0.f) ? z0 : NEG_SLOPE * z0;
            z1 = (z1 > 0.f) ? z1 : NEG_SLOPE * z1;
            w0 = __expf(z0 - M0) * inv0;
            w1 = __expf(z1 - M1) * inv1;
        }
        const float* row = g_xp + (size_t)s * HD;
#pragma unroll
        for (int u = 0; u < 3; u++) {
            int c = t + 128 * u;
            if (c < DIM) {
                acc0[u] = fmaf(w0, row[c], acc0[u]);
                acc1[u] = fmaf(w1, row[DIM + c], acc1[u]);
            }
        }
    }

    // ---- epilogue: head mean + bias + relu + dot(lin_w) ----
    float part = 0.f;
#pragma unroll
    for (int u = 0; u < 3; u++) {
        int c = t + 128 * u;
        if (c < DIM) {
            float v = 0.5f * (acc0[u] + acc1[u]) + bias[c];
            v = fmaxf(v, 0.f);
            part = fmaf(v, lin_w[c], part);
        }
    }
    r0[t] = part;
    __syncthreads();
#pragma unroll
    for (int s = 64; s > 0; s >>= 1) {
        if (t < s) r0[t] += r0[t + s];
        __syncthreads();
    }
    if (t == 0) out[node] = r0[0] + lin_b[0];
}

// ============================================================
// launch — kernel launches ONLY (graph-capturable)
// ============================================================
extern "C" void kernel_launch(void* const* d_in, const int* in_sizes, int n_in,
                              void* d_out, int out_size) {
    const float* x       = (const float*)d_in[0];
    const int*   ei      = (const int*)d_in[1];   // int32 (JAX x64 disabled)
    const float* W       = (const float*)d_in[2];
    const float* att_src = (const float*)d_in[3];
    const float* att_dst = (const float*)d_in[4];
    const float* bias    = (const float*)d_in[5];
    const float* lin_w   = (const float*)d_in[6];
    const float* lin_b   = (const float*)d_in[7];
    float*       out     = (float*)d_out;

    const int n = in_sizes[0] / DIM;       // 20000
    const int e = in_sizes[1] / 2;         // 320000
    const int total = e + n;

    // 1) projection GEMM
    {
        dim3 grid((HD + BN - 1) / BN, (n + BM - 1) / BM);
        gemm_kernel<<<grid, 256>>>(x, W, n);
    }
    // 2) per-node logits
    {
        int threads = 256;
        int blocks = (n * 32 + threads - 1) / threads;
        logits_kernel<<<blocks, threads>>>(att_src, att_dst, n);
    }
    // 3) zero degrees
    zero_deg_kernel<<<(n + 255) / 256, 256>>>(n);
    // 4) histogram
    hist_kernel<<<(total + 255) / 256, 256>>>(ei, e, n);
    // 5) scan
    scan_kernel<<<1, 1024>>>(n);
    // 6) scatter to CSR
    scatter_kernel<<<(total + 255) / 256, 256>>>(ei, e, n);
    // 7) fused softmax + aggregation + epilogue
    agg_kernel<<<n, 128>>>(bias, lin_w, lin_b, out, n);
}

// round 5
// speedup vs baseline: 1.3814x; 1.3814x over previous
#include <cuda_runtime.h>
#include <cuda_bf16.h>

// Problem constants (shapes fixed by the dataset)
#define NMAX 20000
#define EMAX 320000
#define DIM  300
#define HD   600            // H * DIM, H = 2
#define ETMAX (EMAX + NMAX) // edges + self loops
#define NEG_SLOPE 0.2f

// -------- device scratch (static) --------
__device__ float g_xp[(size_t)NMAX * HD];   // projected features [N, H*D] = 48 MB
__device__ float g_asrc[NMAX * 2];
__device__ float g_adst[NMAX * 2];
__device__ int   g_deg[NMAX];
__device__ int   g_offs[NMAX + 1];
__device__ int   g_cursor[NMAX + 1];
__device__ int   g_csr_src[ETMAX];

// ============================================================
// Kernel 1: tiled fp32 GEMM  g_xp[M,600] = A[M,300] * B[300,600]
//   128x128 tile, BK=20, 8x8 microtile, float4 everywhere.
// ============================================================
#define BM 128
#define BN 128
#define BK 20
__global__ void __launch_bounds__(256)
gemm_kernel(const float* __restrict__ A,
            const float* __restrict__ B, int M) {
    __shared__ float As[BK][BM];   // 10 KB
    __shared__ float Bs[BK][BN];   // 10 KB

    const int tid = threadIdx.x;
    const int tx = tid & 15;          // 0..15 -> 8 cols each
    const int ty = tid >> 4;          // 0..15 -> 8 rows each
    const int row0 = blockIdx.y * BM;
    const int col0 = blockIdx.x * BN;

    float acc[8][8];
#pragma unroll
    for (int i = 0; i < 8; i++)
#pragma unroll
        for (int j = 0; j < 8; j++) acc[i][j] = 0.f;

    for (int k0 = 0; k0 < DIM; k0 += BK) {
        // --- load A tile: BM x BK = 2560 floats = 640 float4 ---
#pragma unroll
        for (int i = tid; i < (BM * BK) / 4; i += 256) {
            int row = i / (BK / 4);       // 0..127
            int kq  = i % (BK / 4);       // 0..4
            int gr = row0 + row;
            float4 v = make_float4(0.f, 0.f, 0.f, 0.f);
            if (gr < M)
                v = *(const float4*)&A[(size_t)gr * DIM + k0 + kq * 4];
            As[kq * 4 + 0][row] = v.x;
            As[kq * 4 + 1][row] = v.y;
            As[kq * 4 + 2][row] = v.z;
            As[kq * 4 + 3][row] = v.w;
        }
        // --- load B tile: BK x BN = 2560 floats = 640 float4 ---
#pragma unroll
        for (int i = tid; i < (BK * BN) / 4; i += 256) {
            int row = i / (BN / 4);       // 0..19
            int cq  = i % (BN / 4);       // 0..31
            int gc = col0 + cq * 4;
            float4 v = make_float4(0.f, 0.f, 0.f, 0.f);
            if (gc < HD)                  // HD and strides are /4 => all-or-nothing
                v = *(const float4*)&B[(size_t)(k0 + row) * HD + gc];
            *(float4*)&Bs[row][cq * 4] = v;
        }
        __syncthreads();
#pragma unroll
        for (int k = 0; k < BK; k++) {
            float a[8], b[8];
            *(float4*)&a[0] = *(const float4*)&As[k][ty * 8];
            *(float4*)&a[4] = *(const float4*)&As[k][ty * 8 + 4];
            *(float4*)&b[0] = *(const float4*)&Bs[k][tx * 8];
            *(float4*)&b[4] = *(const float4*)&Bs[k][tx * 8 + 4];
#pragma unroll
            for (int i = 0; i < 8; i++)
#pragma unroll
                for (int j = 0; j < 8; j++)
                    acc[i][j] = fmaf(a[i], b[j], acc[i][j]);
        }
        __syncthreads();
    }
    // --- write back (float4, all-or-nothing col validity) ---
#pragma unroll
    for (int i = 0; i < 8; i++) {
        int r = row0 + ty * 8 + i;
        if (r >= M) continue;
#pragma unroll
        for (int j4 = 0; j4 < 2; j4++) {
            int c = col0 + tx * 8 + j4 * 4;
            if (c < HD)
                *(float4*)&g_xp[(size_t)r * HD + c] =
                    make_float4(acc[i][j4 * 4], acc[i][j4 * 4 + 1],
                                acc[i][j4 * 4 + 2], acc[i][j4 * 4 + 3]);
        }
    }
}

// ============================================================
// Kernel 2: per-node attention logits (warp per node)
// ============================================================
__global__ void logits_kernel(const float* __restrict__ att_src,
                              const float* __restrict__ att_dst, int n) {
    int gtid = blockIdx.x * blockDim.x + threadIdx.x;
    int node = gtid >> 5;
    int lane = gtid & 31;
    if (node >= n) return;
    const float* row = g_xp + (size_t)node * HD;
    float s0 = 0.f, s1 = 0.f, d0 = 0.f, d1 = 0.f;
    for (int c = lane; c < DIM; c += 32) {
        float v0 = row[c], v1 = row[DIM + c];
        s0 += v0 * att_src[c];
        s1 += v1 * att_src[DIM + c];
        d0 += v0 * att_dst[c];
        d1 += v1 * att_dst[DIM + c];
    }
#pragma unroll
    for (int o = 16; o > 0; o >>= 1) {
        s0 += __shfl_down_sync(0xffffffffu, s0, o);
        s1 += __shfl_down_sync(0xffffffffu, s1, o);
        d0 += __shfl_down_sync(0xffffffffu, d0, o);
        d1 += __shfl_down_sync(0xffffffffu, d1, o);
    }
    if (lane == 0) {
        g_asrc[node * 2 + 0] = s0;
        g_asrc[node * 2 + 1] = s1;
        g_adst[node * 2 + 0] = d0;
        g_adst[node * 2 + 1] = d1;
    }
}

// ============================================================
// Kernel 3: zero degree array
// ============================================================
__global__ void zero_deg_kernel(int n) {
    int i = blockIdx.x * blockDim.x + threadIdx.x;
    if (i < n) g_deg[i] = 0;
}

// ============================================================
// Kernel 4: histogram of dst (edges + self loops) — edge_index is int32
// ============================================================
__global__ void hist_kernel(const int* __restrict__ ei, int e, int n) {
    int i = blockIdx.x * blockDim.x + threadIdx.x;
    int total = e + n;
    if (i >= total) return;
    int d = (i < e) ? ei[e + i] : (i - e);
    atomicAdd(&g_deg[d], 1);
}

// ============================================================
// Kernel 5: two-level single-block scan -> offsets + cursor init
//   Each thread serially sums ~20 elems, one 1024-wide scan of
//   partials, then serial writeback. ~12 barrier rounds total.
// ============================================================
__global__ void scan_kernel(int n) {
    __shared__ int sh[1024];
    int t = threadIdx.x;
    int per = (n + 1023) / 1024;
    int base = t * per;

    int sum = 0;
    for (int i = 0; i < per; i++) {
        int idx = base + i;
        if (idx < n) sum += g_deg[idx];
    }
    sh[t] = sum;
    __syncthreads();
#pragma unroll
    for (int off = 1; off < 1024; off <<= 1) {
        int add = (t >= off) ? sh[t - off] : 0;
        __syncthreads();
        sh[t] += add;
        __syncthreads();
    }
    int run = sh[t] - sum;   // exclusive prefix of this thread's chunk
    if (t == 0) { g_offs[0] = 0; g_cursor[0] = 0; }
    for (int i = 0; i < per; i++) {
        int idx = base + i;
        if (idx < n) {
            run += g_deg[idx];
            g_offs[idx + 1] = run;
            g_cursor[idx + 1] = run;
        }
    }
}

// ============================================================
// Kernel 6: scatter edges into CSR-by-dst
// ============================================================
__global__ void scatter_kernel(const int* __restrict__ ei, int e, int n) {
    int i = blockIdx.x * blockDim.x + threadIdx.x;
    int total = e + n;
    if (i >= total) return;
    int s, d;
    if (i < e) {
        s = ei[i];
        d = ei[e + i];
    } else {
        s = d = i - e;
    }
    int pos = atomicAdd(&g_cursor[d], 1);
    g_csr_src[pos] = s;
}

// ============================================================
// Kernel 7: fused segment softmax + weighted aggregation + epilogue
// ============================================================
#define CAP 256
__global__ void agg_kernel(const float* __restrict__ bias,
                           const float* __restrict__ lin_w,
                           const float* __restrict__ lin_b,
                           float* __restrict__ out, int n) {
    int node = blockIdx.x;
    if (node >= n) return;
    int t = threadIdx.x;

    int beg = g_offs[node];
    int deg = g_offs[node + 1] - beg;

    float ad0 = g_adst[node * 2 + 0];
    float ad1 = g_adst[node * 2 + 1];

    __shared__ float sh_e0[CAP];
    __shared__ float sh_e1[CAP];
    __shared__ int   sh_s[CAP];
    __shared__ float r0[128];
    __shared__ float r1[128];

    // ---- phase 1: logits + per-head max ----
    float m0 = -3.4e38f, m1 = -3.4e38f;
    for (int j = t; j < deg; j += 128) {
        int s = g_csr_src[beg + j];
        float z0 = g_asrc[s * 2 + 0] + ad0;
        float z1 = g_asrc[s * 2 + 1] + ad1;
        z0 = (z0 > 0.f) ? z0 : NEG_SLOPE * z0;
        z1 = (z1 > 0.f) ? z1 : NEG_SLOPE * z1;
        m0 = fmaxf(m0, z0);
        m1 = fmaxf(m1, z1);
        if (j < CAP) { sh_e0[j] = z0; sh_e1[j] = z1; sh_s[j] = s; }
    }
    r0[t] = m0; r1[t] = m1;
    __syncthreads();
#pragma unroll
    for (int s = 64; s > 0; s >>= 1) {
        if (t < s) {
            r0[t] = fmaxf(r0[t], r0[t + s]);
            r1[t] = fmaxf(r1[t], r1[t + s]);
        }
        __syncthreads();
    }
    float M0 = r0[0], M1 = r1[0];
    __syncthreads();

    // ---- phase 2: exp and sum ----
    float s0 = 0.f, s1 = 0.f;
    for (int j = t; j < deg; j += 128) {
        float e0, e1;
        if (j < CAP) {
            e0 = __expf(sh_e0[j] - M0);
            e1 = __expf(sh_e1[j] - M1);
            sh_e0[j] = e0;
            sh_e1[j] = e1;
        } else {
            int s = g_csr_src[beg + j];
            float z0 = g_asrc[s * 2 + 0] + ad0;
            float z1 = g_asrc[s * 2 + 1] + ad1;
            z0 = (z0 > 0.f) ? z0 : NEG_SLOPE * z0;
            z1 = (z1 > 0.f) ? z1 : NEG_SLOPE * z1;
            e0 = __expf(z0 - M0);
            e1 = __expf(z1 - M1);
        }
        s0 += e0; s1 += e1;
    }
    r0[t] = s0; r1[t] = s1;
    __syncthreads();
#pragma unroll
    for (int s = 64; s > 0; s >>= 1) {
        if (t < s) {
            r0[t] += r0[t + s];
            r1[t] += r1[t + s];
        }
        __syncthreads();
    }
    float inv0 = 1.f / r0[0];
    float inv1 = 1.f / r1[0];
    __syncthreads();

    // ---- phase 3: weighted gather of xp rows ----
    float acc0[3] = {0.f, 0.f, 0.f};
    float acc1[3] = {0.f, 0.f, 0.f};
    for (int j = 0; j < deg; j++) {
        int s;
        float w0, w1;
        if (j < CAP) {
            s = sh_s[j];
            w0 = sh_e0[j] * inv0;
            w1 = sh_e1[j] * inv1;
        } else {
            s = g_csr_src[beg + j];
            float z0 = g_asrc[s * 2 + 0] + ad0;
            float z1 = g_asrc[s * 2 + 1] + ad1;
            z0 = (z0 > 0.f) ? z0 : NEG_SLOPE * z0;
            z1 = (z1 > 0.f) ? z1 : NEG_SLOPE * z1;
            w0 = __expf(z0 - M0) * inv0;
            w1 = __expf(z1 - M1) * inv1;
        }
        const float* row = g_xp + (size_t)s * HD;
#pragma unroll
        for (int u = 0; u < 3; u++) {
            int c = t + 128 * u;
            if (c < DIM) {
                acc0[u] = fmaf(w0, row[c], acc0[u]);
                acc1[u] = fmaf(w1, row[DIM + c], acc1[u]);
            }
        }
    }

    // ---- epilogue: head mean + bias + relu + dot(lin_w) ----
    float part = 0.f;
#pragma unroll
    for (int u = 0; u < 3; u++) {
        int c = t + 128 * u;
        if (c < DIM) {
            float v = 0.5f * (acc0[u] + acc1[u]) + bias[c];
            v = fmaxf(v, 0.f);
            part = fmaf(v, lin_w[c], part);
        }
    }
    r0[t] = part;
    __syncthreads();
#pragma unroll
    for (int s = 64; s > 0; s >>= 1) {
        if (t < s) r0[t] += r0[t + s];
        __syncthreads();
    }
    if (t == 0) out[node] = r0[0] + lin_b[0];
}

// ============================================================
// launch — kernel launches ONLY (graph-capturable)
// ============================================================
extern "C" void kernel_launch(void* const* d_in, const int* in_sizes, int n_in,
                              void* d_out, int out_size) {
    const float* x       = (const float*)d_in[0];
    const int*   ei      = (const int*)d_in[1];   // int32
    const float* W       = (const float*)d_in[2];
    const float* att_src = (const float*)d_in[3];
    const float* att_dst = (const float*)d_in[4];
    const float* bias    = (const float*)d_in[5];
    const float* lin_w   = (const float*)d_in[6];
    const float* lin_b   = (const float*)d_in[7];
    float*       out     = (float*)d_out;

    const int n = in_sizes[0] / DIM;       // 20000
    const int e = in_sizes[1] / 2;         // 320000
    const int total = e + n;

    // 1) projection GEMM
    {
        dim3 grid((HD + BN - 1) / BN, (n + BM - 1) / BM);
        gemm_kernel<<<grid, 256>>>(x, W, n);
    }
    // 2) per-node logits
    {
        int threads = 256;
        int blocks = (n * 32 + threads - 1) / threads;
        logits_kernel<<<blocks, threads>>>(att_src, att_dst, n);
    }
    // 3) zero degrees
    zero_deg_kernel<<<(n + 255) / 256, 256>>>(n);
    // 4) histogram
    hist_kernel<<<(total + 255) / 256, 256>>>(ei, e, n);
    // 5) scan
    scan_kernel<<<1, 1024>>>(n);
    // 6) scatter to CSR
    scatter_kernel<<<(total + 255) / 256, 256>>>(ei, e, n);
    // 7) fused softmax + aggregation + epilogue
    agg_kernel<<<n, 128>>>(bias, lin_w, lin_b, out, n);
}